// round 12
// baseline (speedup 1.0000x reference)
#include <cuda_runtime.h>
#include <cuda_bf16.h>
#include <cstdint>

#define Hc   256
#define Bc   64
#define Tc   256
#define Ec   300
#define NB   128
#define NT   384
typedef unsigned long long ull;
typedef unsigned int u32;

// ---------------- device scratch ----------------
__device__ float g_pre0[(size_t)Tc * 1024 * Bc];   // [t][gatecol][b]
__device__ u32 g_h0p[2][Bc * Hc];                  // packed split h0 [slot][b][unit]
__device__ u32 g_h1p[2][Bc * Hc];                  // packed split h1
__device__ unsigned g_flags[NB * 8];
__device__ unsigned g_gen;
__device__ int g_is64;

// ---------------- helpers ----------------
__device__ __forceinline__ void fma2(ull& d, ull a, ull b) {
    asm("fma.rn.f32x2 %0, %1, %2, %0;" : "+l"(d) : "l"(a), "l"(b));
}
__device__ __forceinline__ ull dup2(float x) {
    ull r; asm("mov.b64 %0, {%1, %1};" : "=l"(r) : "f"(x)); return r;
}
__device__ __forceinline__ float2 unpk(ull v) {
    float2 r; asm("mov.b64 {%0, %1}, %2;" : "=f"(r.x), "=f"(r.y) : "l"(v)); return r;
}
__device__ __forceinline__ float sigf(float x)  { return 1.0f / (1.0f + __expf(-x)); }
__device__ __forceinline__ float tanhf_(float x){ return 2.0f / (1.0f + __expf(-2.0f * x)) - 1.0f; }
__device__ __forceinline__ void st_rel(unsigned* p, unsigned v) {
    asm volatile("st.release.gpu.global.u32 [%0], %1;" :: "l"(p), "r"(v) : "memory");
}
__device__ __forceinline__ unsigned ld_acq(const unsigned* p) {
    unsigned v; asm volatile("ld.acquire.gpu.global.u32 %0, [%1];" : "=r"(v) : "l"(p) : "memory");
    return v;
}
__device__ __forceinline__ u32 prmt(u32 a, u32 b, u32 s) {
    u32 r; asm("prmt.b32 %0, %1, %2, %3;" : "=r"(r) : "r"(a), "r"(b), "r"(s)); return r;
}
__device__ __forceinline__ void mma16816(float* d, u32 a0, u32 a1, u32 a2, u32 a3,
                                         u32 b0, u32 b1) {
    asm("mma.sync.aligned.m16n8k16.row.col.f32.bf16.bf16.f32 "
        "{%0,%1,%2,%3}, {%4,%5,%6,%7}, {%8,%9}, {%0,%1,%2,%3};"
        : "+f"(d[0]), "+f"(d[1]), "+f"(d[2]), "+f"(d[3])
        : "r"(a0), "r"(a1), "r"(a2), "r"(a3), "r"(b0), "r"(b1));
}
__device__ __forceinline__ void split(float v, u32& hb, u32& lb) {
    __nv_bfloat16 h = __float2bfloat16(v);
    float r = v - __bfloat162float(h);
    hb = (u32)__bfloat16_as_ushort(h);
    lb = (u32)__bfloat16_as_ushort(__float2bfloat16(r));
}
__device__ __forceinline__ u32 packsplit(float v) {
    u32 hb, lb; split(v, hb, lb); return hb | (lb << 16);
}

// Grid barrier (R6 proven): per-CTA release flag; CTA0/warp0 aggregates, one gen word.
__device__ __forceinline__ void gbar(int bid, int tid, unsigned epoch) {
    __syncthreads();
    if (tid == 0) st_rel(&g_flags[bid * 8], epoch);
    if (bid == 0 && tid < 32) {
        bool ok;
        do {
            unsigned v0 = ld_acq(&g_flags[tid * 8]);
            unsigned v1 = ld_acq(&g_flags[(tid + 32) * 8]);
            unsigned v2 = ld_acq(&g_flags[(tid + 64) * 8]);
            unsigned v3 = ld_acq(&g_flags[(tid + 96) * 8]);
            ok = (v0 >= epoch) & (v1 >= epoch) & (v2 >= epoch) & (v3 >= epoch);
        } while (!__all_sync(0xffffffffu, ok));
        if (tid == 0) st_rel(&g_gen, epoch);
    } else if (tid == 0) {
        while (ld_acq(&g_gen) < epoch) {}
    }
    __syncthreads();
}

// ---------------- int32/int64 token detector ----------------
__global__ void k_detect(const int* __restrict__ x) {
    int v = 0;
    for (int i = threadIdx.x * 2 + 1; i < Bc * Tc; i += 1024) v |= x[i];
    int any = __syncthreads_or(v);
    if (threadIdx.x == 0) g_is64 = (any == 0) ? 1 : 0;
}

// ---------------- k_pre: x-projection (unchanged, proven) ----------------
__global__ void __launch_bounds__(256) k_pre(const int* __restrict__ x,
                                             const float* __restrict__ emb,
                                             const float* __restrict__ W0,
                                             const float* __restrict__ b0) {
    extern __shared__ float semb[];
    const int t = blockIdx.y, ct = blockIdx.x;
    const int tid = threadIdx.x, lane = tid & 31, w = tid >> 5;
    const int is64 = g_is64;

    for (int bb = w; bb < Bc; bb += 8) {
        int idx = bb * Tc + t;
        int tok = is64 ? x[2 * idx] : x[idx];
        const float* er = emb + (size_t)tok * Ec;
        for (int e = lane; e < Ec; e += 32) semb[e * 66 + bb] = er[e];
    }
    __syncthreads();

    const int cg = tid & 63, bg = tid >> 6;
    const int c0 = ct * 256 + cg * 4;

    ull a0[8], a1[8], a2[8], a3[8];
#pragma unroll
    for (int j = 0; j < 8; j++) { a0[j] = 0ull; a1[j] = 0ull; a2[j] = 0ull; a3[j] = 0ull; }

#pragma unroll 4
    for (int e = 0; e < Ec; e++) {
        float4 wv = __ldg((const float4*)(W0 + (size_t)e * 1024 + c0));
        ull w0 = dup2(wv.x), w1 = dup2(wv.y), w2 = dup2(wv.z), w3 = dup2(wv.w);
        const ull* sp = (const ull*)(semb + e * 66 + bg * 16);
        ull p0 = sp[0], p1 = sp[1], p2 = sp[2], p3 = sp[3];
        ull p4 = sp[4], p5 = sp[5], p6 = sp[6], p7 = sp[7];
        fma2(a0[0], p0, w0); fma2(a0[1], p1, w0); fma2(a0[2], p2, w0); fma2(a0[3], p3, w0);
        fma2(a0[4], p4, w0); fma2(a0[5], p5, w0); fma2(a0[6], p6, w0); fma2(a0[7], p7, w0);
        fma2(a1[0], p0, w1); fma2(a1[1], p1, w1); fma2(a1[2], p2, w1); fma2(a1[3], p3, w1);
        fma2(a1[4], p4, w1); fma2(a1[5], p5, w1); fma2(a1[6], p6, w1); fma2(a1[7], p7, w1);
        fma2(a2[0], p0, w2); fma2(a2[1], p1, w2); fma2(a2[2], p2, w2); fma2(a2[3], p3, w2);
        fma2(a2[4], p4, w2); fma2(a2[5], p5, w2); fma2(a2[6], p6, w2); fma2(a2[7], p7, w2);
        fma2(a3[0], p0, w3); fma2(a3[1], p1, w3); fma2(a3[2], p2, w3); fma2(a3[3], p3, w3);
        fma2(a3[4], p4, w3); fma2(a3[5], p5, w3); fma2(a3[6], p6, w3); fma2(a3[7], p7, w3);
    }

    float4 bb4 = __ldg((const float4*)(b0 + c0));
    float bs[4] = {bb4.x, bb4.y, bb4.z, bb4.w};
    ull* accs[4] = {a0, a1, a2, a3};
#pragma unroll
    for (int j = 0; j < 4; j++) {
        float* op = g_pre0 + ((size_t)t * 1024 + c0 + j) * Bc + bg * 16;
#pragma unroll
        for (int p = 0; p < 8; p++) {
            float2 v = unpk(accs[j][p]);
            v.x += bs[j]; v.y += bs[j];
            *(float2*)(op + 2 * p) = v;
        }
    }
}

// ---------------- k_rnn: tensor-core recurrence ----------------
// 128 CTAs x 384 thr (12 warps). CTA owns 2 units/layer x 64 batches.
// Warp wid: m-tile = wid&3 (16 batches); role = wid>>2: 0=W0h (layer0 gates),
// 1=W1x (layer1 x-proj), 2=W1h (layer1 h-proj). Each warp: full K=256,
// 16 k-tiles x 3 split-passes of mma.m16n8k16 bf16 -> fp32 D (no reduction).
// h stored packed u32 (lo<<16|hi) split-bf16; A frags via LDG.64 + PRMT.
__global__ void __launch_bounds__(NT) k_rnn(const float* __restrict__ W0,
                                            const float* __restrict__ W1,
                                            const float* __restrict__ b1,
                                            float* __restrict__ out) {
    __shared__ float gg0[Bc * 10], ggX[Bc * 10], gg1[Bc * 10], b1sh[8];

    const int tid = threadIdx.x, lane = tid & 31, wid = tid >> 5, bid = blockIdx.x;
    const int role = wid >> 2;

    // ---- persistent weight B-fragments (64 regs/thread) ----
    // B frag (col-major KxN): thread n = lane>>2, k0 = (lane&3)*2; b_j covers k0+8j.
    // local col n: gate g=n>>1, unit u=n&1 -> global G = g*256 + bid*2 + u.
    u32 Bh[16][2], Bl[16][2];
    {
        const int n = lane >> 2, k0 = (lane & 3) * 2;
        const int G = (n >> 1) * 256 + bid * 2 + (n & 1);
        const float* Wp = (role == 0) ? W0 + (size_t)Ec * 1024
                        : (role == 1) ? W1
                                      : W1 + (size_t)Hc * 1024;
#pragma unroll
        for (int kt = 0; kt < 16; kt++)
#pragma unroll
            for (int j = 0; j < 2; j++) {
                int k = kt * 16 + j * 8 + k0;
                u32 h0b, l0b, h1b, l1b;
                split(__ldg(Wp + (size_t)k * 1024 + G), h0b, l0b);
                split(__ldg(Wp + (size_t)(k + 1) * 1024 + G), h1b, l1b);
                Bh[kt][j] = h0b | (h1b << 16);
                Bl[kt][j] = l0b | (l1b << 16);
            }
    }
    if (tid < 8) {
        int c = tid, G = (c >> 1) * 256 + bid * 2 + (c & 1);
        b1sh[c] = __ldg(b1 + G);
    }
    // zero owned h entries in both slots
    if (tid < 256) {
        int l = tid >> 7, u = (tid >> 6) & 1, b = tid & 63;
        int off = b * Hc + bid * 2 + u;
        if (l == 0) { g_h0p[0][off] = 0u; g_h0p[1][off] = 0u; }
        else        { g_h1p[0][off] = 0u; g_h1p[1][off] = 0u; }
    }
    float creg = 0.f;
    gbar(bid, tid, 1u);

    const int l_ = tid >> 7, u_ = (tid >> 6) & 1, b_ = tid & 63;   // activation: tid<256
    const int U_ = bid * 2 + u_;

    for (int s = 0; s <= Tc; s++) {
        // pf prefetch for layer0 activation threads
        float pf[4] = {0.f, 0.f, 0.f, 0.f};
        if (tid < 128 && s < Tc) {
#pragma unroll
            for (int g = 0; g < 4; g++)
                pf[g] = __ldg(g_pre0 + ((size_t)s * 1024 + g * 256 + U_) * Bc + b_);
        }

        const bool go = (role == 0) ? (s < Tc) : (s >= 1);
        if (go) {
            const u32* hp = (role < 2) ? g_h0p[s & 1] : g_h1p[s & 1];
            const int r = (wid & 3) * 16 + (lane >> 2), c0 = (lane & 3) * 2;
            const u32* base0 = hp + r * Hc;
            const u32* base1 = hp + (r + 8) * Hc;
            float d[4] = {0.f, 0.f, 0.f, 0.f};
#pragma unroll
            for (int kt = 0; kt < 16; kt++) {
                int c = kt * 16 + c0;
                ull q0 = __ldcg((const ull*)(base0 + c));
                ull q1 = __ldcg((const ull*)(base1 + c));
                ull q2 = __ldcg((const ull*)(base0 + c + 8));
                ull q3 = __ldcg((const ull*)(base1 + c + 8));
                u32 ah0 = prmt((u32)q0, (u32)(q0 >> 32), 0x5410);
                u32 al0 = prmt((u32)q0, (u32)(q0 >> 32), 0x7632);
                u32 ah1 = prmt((u32)q1, (u32)(q1 >> 32), 0x5410);
                u32 al1 = prmt((u32)q1, (u32)(q1 >> 32), 0x7632);
                u32 ah2 = prmt((u32)q2, (u32)(q2 >> 32), 0x5410);
                u32 al2 = prmt((u32)q2, (u32)(q2 >> 32), 0x7632);
                u32 ah3 = prmt((u32)q3, (u32)(q3 >> 32), 0x5410);
                u32 al3 = prmt((u32)q3, (u32)(q3 >> 32), 0x7632);
                mma16816(d, ah0, ah1, ah2, ah3, Bh[kt][0], Bh[kt][1]);  // hi*hi
                mma16816(d, al0, al1, al2, al3, Bh[kt][0], Bh[kt][1]);  // lo*hi
                mma16816(d, ah0, ah1, ah2, ah3, Bl[kt][0], Bl[kt][1]);  // hi*lo
            }
            // D: thread holds (r,c0),(r,c0+1),(r+8,c0),(r+8,c0+1) of its n-tile
            float* gg = (role == 0) ? gg0 : (role == 1) ? ggX : gg1;
            float* gp = gg + r * 10 + c0;
            *(float2*)gp            = make_float2(d[0], d[1]);
            *(float2*)(gp + 8 * 10) = make_float2(d[2], d[3]);
        }
        __syncthreads();

        const bool active = (tid < 256) && ((l_ == 0) ? (s < Tc) : (s >= 1));
        if (active) {
            float gate[4];
#pragma unroll
            for (int g = 0; g < 4; g++) {
                int c = g * 2 + u_;
                gate[g] = (l_ == 0) ? (gg0[b_ * 10 + c] + pf[g])
                                    : (ggX[b_ * 10 + c] + gg1[b_ * 10 + c] + b1sh[c]);
            }
            float ii = sigf(gate[0]);
            float jj = tanhf_(gate[1]);
            float ff = sigf(gate[2] + 1.0f);       // FORGET_BIAS
            float oo = sigf(gate[3]);
            creg = creg * ff + ii * jj;
            float h = tanhf_(creg) * oo;
            int off = b_ * Hc + U_;
            if (l_ == 0) {
                g_h0p[(s + 1) & 1][off] = packsplit(h);
            } else if (s < Tc) {
                g_h1p[(s + 1) & 1][off] = packsplit(h);
            } else {
                out[off] = h;                       // h1[T-1]
            }
        }
        if (s < Tc) gbar(bid, tid, (unsigned)(s + 2));
    }
}

// ---------------- k_reset (before k_rnn in-stream) ----------------
__global__ void k_reset() {
    int i = blockIdx.x * blockDim.x + threadIdx.x;
    if (i < NB * 8) g_flags[i] = 0u;
    if (i == 0) g_gen = 0u;
}

// ---------------- host launcher ----------------
extern "C" void kernel_launch(void* const* d_in, const int* in_sizes, int n_in,
                              void* d_out, int out_size) {
    const int*   x   = (const int*)d_in[0];
    const float* emb = (const float*)d_in[1];
    const float* W0  = (const float*)d_in[2];
    const float* b0  = (const float*)d_in[3];
    const float* W1  = (const float*)d_in[4];
    const float* b1  = (const float*)d_in[5];
    float*       out = (float*)d_out;
    (void)in_sizes; (void)n_in; (void)out_size;

    const int smem_pre = Ec * 66 * 4;   // 79200 B

    static bool attr_done = false;
    if (!attr_done) {
        cudaFuncSetAttribute(k_pre, cudaFuncAttributeMaxDynamicSharedMemorySize, smem_pre);
        attr_done = true;
    }

    k_detect<<<1, 512>>>(x);
    k_pre<<<dim3(4, 256), 256, smem_pre>>>(x, emb, W0, b0);
    k_reset<<<4, 256>>>();
    k_rnn<<<NB, NT>>>(W0, W1, b1, out);
}

// round 13
// speedup vs baseline: 1.2044x; 1.2044x over previous
#include <cuda_runtime.h>
#include <cuda_bf16.h>
#include <cstdint>

#define Hc   256
#define Bc   64
#define Tc   256
#define Ec   300
#define NB   128
#define NT   384
#define SROW 260          // padded smem row stride (u32) for 2-way-max conflicts
typedef unsigned long long ull;
typedef unsigned int u32;

// ---------------- device scratch ----------------
__device__ float g_pre0[(size_t)Tc * 1024 * Bc];   // [t][gatecol][b]
__device__ u32 g_h0p[2][Bc * Hc];                  // packed split h0 [slot][b][unit]
__device__ u32 g_h1p[2][Bc * Hc];                  // packed split h1
__device__ unsigned g_flags[NB * 8];
__device__ unsigned g_gen;
__device__ int g_is64;

// ---------------- helpers ----------------
__device__ __forceinline__ void fma2(ull& d, ull a, ull b) {
    asm("fma.rn.f32x2 %0, %1, %2, %0;" : "+l"(d) : "l"(a), "l"(b));
}
__device__ __forceinline__ ull dup2(float x) {
    ull r; asm("mov.b64 %0, {%1, %1};" : "=l"(r) : "f"(x)); return r;
}
__device__ __forceinline__ float2 unpk(ull v) {
    float2 r; asm("mov.b64 {%0, %1}, %2;" : "=f"(r.x), "=f"(r.y) : "l"(v)); return r;
}
__device__ __forceinline__ float sigf(float x)  { return 1.0f / (1.0f + __expf(-x)); }
__device__ __forceinline__ float tanhf_(float x){ return 2.0f / (1.0f + __expf(-2.0f * x)) - 1.0f; }
__device__ __forceinline__ void st_rel(unsigned* p, unsigned v) {
    asm volatile("st.release.gpu.global.u32 [%0], %1;" :: "l"(p), "r"(v) : "memory");
}
__device__ __forceinline__ unsigned ld_acq(const unsigned* p) {
    unsigned v; asm volatile("ld.acquire.gpu.global.u32 %0, [%1];" : "=r"(v) : "l"(p) : "memory");
    return v;
}
__device__ __forceinline__ u32 prmt(u32 a, u32 b, u32 s) {
    u32 r; asm("prmt.b32 %0, %1, %2, %3;" : "=r"(r) : "r"(a), "r"(b), "r"(s)); return r;
}
__device__ __forceinline__ void mma16816(float* d, u32 a0, u32 a1, u32 a2, u32 a3,
                                         u32 b0, u32 b1) {
    asm("mma.sync.aligned.m16n8k16.row.col.f32.bf16.bf16.f32 "
        "{%0,%1,%2,%3}, {%4,%5,%6,%7}, {%8,%9}, {%0,%1,%2,%3};"
        : "+f"(d[0]), "+f"(d[1]), "+f"(d[2]), "+f"(d[3])
        : "r"(a0), "r"(a1), "r"(a2), "r"(a3), "r"(b0), "r"(b1));
}
__device__ __forceinline__ void split(float v, u32& hb, u32& lb) {
    __nv_bfloat16 h = __float2bfloat16(v);
    float r = v - __bfloat162float(h);
    hb = (u32)__bfloat16_as_ushort(h);
    lb = (u32)__bfloat16_as_ushort(__float2bfloat16(r));
}
__device__ __forceinline__ u32 packsplit(float v) {
    u32 hb, lb; split(v, hb, lb); return hb | (lb << 16);
}

// Grid barrier (R6 proven)
__device__ __forceinline__ void gbar(int bid, int tid, unsigned epoch) {
    __syncthreads();
    if (tid == 0) st_rel(&g_flags[bid * 8], epoch);
    if (bid == 0 && tid < 32) {
        bool ok;
        do {
            unsigned v0 = ld_acq(&g_flags[tid * 8]);
            unsigned v1 = ld_acq(&g_flags[(tid + 32) * 8]);
            unsigned v2 = ld_acq(&g_flags[(tid + 64) * 8]);
            unsigned v3 = ld_acq(&g_flags[(tid + 96) * 8]);
            ok = (v0 >= epoch) & (v1 >= epoch) & (v2 >= epoch) & (v3 >= epoch);
        } while (!__all_sync(0xffffffffu, ok));
        if (tid == 0) st_rel(&g_gen, epoch);
    } else if (tid == 0) {
        while (ld_acq(&g_gen) < epoch) {}
    }
    __syncthreads();
}

// ---------------- int32/int64 token detector ----------------
__global__ void k_detect(const int* __restrict__ x) {
    int v = 0;
    for (int i = threadIdx.x * 2 + 1; i < Bc * Tc; i += 1024) v |= x[i];
    int any = __syncthreads_or(v);
    if (threadIdx.x == 0) g_is64 = (any == 0) ? 1 : 0;
}

// ---------------- k_pre: x-projection (proven) ----------------
__global__ void __launch_bounds__(256) k_pre(const int* __restrict__ x,
                                             const float* __restrict__ emb,
                                             const float* __restrict__ W0,
                                             const float* __restrict__ b0) {
    extern __shared__ float semb[];
    const int t = blockIdx.y, ct = blockIdx.x;
    const int tid = threadIdx.x, lane = tid & 31, w = tid >> 5;
    const int is64 = g_is64;

    for (int bb = w; bb < Bc; bb += 8) {
        int idx = bb * Tc + t;
        int tok = is64 ? x[2 * idx] : x[idx];
        const float* er = emb + (size_t)tok * Ec;
        for (int e = lane; e < Ec; e += 32) semb[e * 66 + bb] = er[e];
    }
    __syncthreads();

    const int cg = tid & 63, bg = tid >> 6;
    const int c0 = ct * 256 + cg * 4;

    ull a0[8], a1[8], a2[8], a3[8];
#pragma unroll
    for (int j = 0; j < 8; j++) { a0[j] = 0ull; a1[j] = 0ull; a2[j] = 0ull; a3[j] = 0ull; }

#pragma unroll 4
    for (int e = 0; e < Ec; e++) {
        float4 wv = __ldg((const float4*)(W0 + (size_t)e * 1024 + c0));
        ull w0 = dup2(wv.x), w1 = dup2(wv.y), w2 = dup2(wv.z), w3 = dup2(wv.w);
        const ull* sp = (const ull*)(semb + e * 66 + bg * 16);
        ull p0 = sp[0], p1 = sp[1], p2 = sp[2], p3 = sp[3];
        ull p4 = sp[4], p5 = sp[5], p6 = sp[6], p7 = sp[7];
        fma2(a0[0], p0, w0); fma2(a0[1], p1, w0); fma2(a0[2], p2, w0); fma2(a0[3], p3, w0);
        fma2(a0[4], p4, w0); fma2(a0[5], p5, w0); fma2(a0[6], p6, w0); fma2(a0[7], p7, w0);
        fma2(a1[0], p0, w1); fma2(a1[1], p1, w1); fma2(a1[2], p2, w1); fma2(a1[3], p3, w1);
        fma2(a1[4], p4, w1); fma2(a1[5], p5, w1); fma2(a1[6], p6, w1); fma2(a1[7], p7, w1);
        fma2(a2[0], p0, w2); fma2(a2[1], p1, w2); fma2(a2[2], p2, w2); fma2(a2[3], p3, w2);
        fma2(a2[4], p4, w2); fma2(a2[5], p5, w2); fma2(a2[6], p6, w2); fma2(a2[7], p7, w2);
        fma2(a3[0], p0, w3); fma2(a3[1], p1, w3); fma2(a3[2], p2, w3); fma2(a3[3], p3, w3);
        fma2(a3[4], p4, w3); fma2(a3[5], p5, w3); fma2(a3[6], p6, w3); fma2(a3[7], p7, w3);
    }

    float4 bb4 = __ldg((const float4*)(b0 + c0));
    float bs[4] = {bb4.x, bb4.y, bb4.z, bb4.w};
    ull* accs[4] = {a0, a1, a2, a3};
#pragma unroll
    for (int j = 0; j < 4; j++) {
        float* op = g_pre0 + ((size_t)t * 1024 + c0 + j) * Bc + bg * 16;
#pragma unroll
        for (int p = 0; p < 8; p++) {
            float2 v = unpk(accs[j][p]);
            v.x += bs[j]; v.y += bs[j];
            *(float2*)(op + 2 * p) = v;
        }
    }
}

// ---------------- k_rnn: tensor-core recurrence + smem h staging ----------------
// Same decomposition/fragments as R12 (verified, rel_err 4.4e-6). New: per-step
// bulk copy of h0p/h1p (64KB each) into padded smem; A-frags via LDS not LDG.
__global__ void __launch_bounds__(NT) k_rnn(const float* __restrict__ W0,
                                            const float* __restrict__ W1,
                                            const float* __restrict__ b1,
                                            float* __restrict__ out) {
    extern __shared__ u32 smem[];
    u32* sh0 = smem;                       // [64][SROW] staged h0   66560 B
    u32* sh1 = sh0 + Bc * SROW;            // staged h1              66560 B
    float* gg0 = (float*)(sh1 + Bc * SROW);      // [64][10]   2560 B
    float* ggX = gg0 + Bc * 10;
    float* gg1 = ggX + Bc * 10;
    float* b1sh = gg1 + Bc * 10;

    const int tid = threadIdx.x, lane = tid & 31, wid = tid >> 5, bid = blockIdx.x;
    const int role = wid >> 2;

    // persistent weight B-fragments (verified layout)
    u32 Bh[16][2], Bl[16][2];
    {
        const int n = lane >> 2, k0 = (lane & 3) * 2;
        const int G = (n >> 1) * 256 + bid * 2 + (n & 1);
        const float* Wp = (role == 0) ? W0 + (size_t)Ec * 1024
                        : (role == 1) ? W1
                                      : W1 + (size_t)Hc * 1024;
#pragma unroll
        for (int kt = 0; kt < 16; kt++)
#pragma unroll
            for (int j = 0; j < 2; j++) {
                int k = kt * 16 + j * 8 + k0;
                u32 h0b, l0b, h1b, l1b;
                split(__ldg(Wp + (size_t)k * 1024 + G), h0b, l0b);
                split(__ldg(Wp + (size_t)(k + 1) * 1024 + G), h1b, l1b);
                Bh[kt][j] = h0b | (h1b << 16);
                Bl[kt][j] = l0b | (l1b << 16);
            }
    }
    if (tid < 8) {
        int c = tid, G = (c >> 1) * 256 + bid * 2 + (c & 1);
        b1sh[c] = __ldg(b1 + G);
    }
    if (tid < 256) {
        int l = tid >> 7, u = (tid >> 6) & 1, b = tid & 63;
        int off = b * Hc + bid * 2 + u;
        if (l == 0) { g_h0p[0][off] = 0u; g_h0p[1][off] = 0u; }
        else        { g_h1p[0][off] = 0u; g_h1p[1][off] = 0u; }
    }
    float creg = 0.f;
    gbar(bid, tid, 1u);

    const int l_ = tid >> 7, u_ = (tid >> 6) & 1, b_ = tid & 63;
    const int U_ = bid * 2 + u_;

    for (int s = 0; s <= Tc; s++) {
        float pf[4] = {0.f, 0.f, 0.f, 0.f};
        if (tid < 128 && s < Tc) {
#pragma unroll
            for (int g = 0; g < 4; g++)
                pf[g] = __ldg(g_pre0 + ((size_t)s * 1024 + g * 256 + U_) * Bc + b_);
        }

        // ---- bulk stage h0p/h1p (current slot) into padded smem ----
        {
            const uint4* s0 = (const uint4*)g_h0p[s & 1];
            const uint4* s1 = (const uint4*)g_h1p[s & 1];
#pragma unroll
            for (int it = 0; it < 11; it++) {
                int q = it * NT + tid;                 // uint4 index, 4096 total
                if (q < 4096) {
                    int b = q >> 6, u = (q & 63) * 4;  // 256 u32 per row
                    uint4 v0 = __ldcg(s0 + q);
                    uint4 v1 = __ldcg(s1 + q);
                    *(uint4*)(sh0 + b * SROW + u) = v0;
                    *(uint4*)(sh1 + b * SROW + u) = v1;
                }
            }
        }
        __syncthreads();

        const bool go = (role == 0) ? (s < Tc) : (s >= 1);
        if (go) {
            const u32* hp = (role < 2) ? sh0 : sh1;
            const int r = (wid & 3) * 16 + (lane >> 2), c0 = (lane & 3) * 2;
            const u32* base0 = hp + r * SROW;
            const u32* base1 = hp + (r + 8) * SROW;
            float d[4] = {0.f, 0.f, 0.f, 0.f};
#pragma unroll
            for (int kt = 0; kt < 16; kt++) {
                int c = kt * 16 + c0;
                ull q0 = *(const ull*)(base0 + c);
                ull q1 = *(const ull*)(base1 + c);
                ull q2 = *(const ull*)(base0 + c + 8);
                ull q3 = *(const ull*)(base1 + c + 8);
                u32 ah0 = prmt((u32)q0, (u32)(q0 >> 32), 0x5410);
                u32 al0 = prmt((u32)q0, (u32)(q0 >> 32), 0x7632);
                u32 ah1 = prmt((u32)q1, (u32)(q1 >> 32), 0x5410);
                u32 al1 = prmt((u32)q1, (u32)(q1 >> 32), 0x7632);
                u32 ah2 = prmt((u32)q2, (u32)(q2 >> 32), 0x5410);
                u32 al2 = prmt((u32)q2, (u32)(q2 >> 32), 0x7632);
                u32 ah3 = prmt((u32)q3, (u32)(q3 >> 32), 0x5410);
                u32 al3 = prmt((u32)q3, (u32)(q3 >> 32), 0x7632);
                mma16816(d, ah0, ah1, ah2, ah3, Bh[kt][0], Bh[kt][1]);
                mma16816(d, al0, al1, al2, al3, Bh[kt][0], Bh[kt][1]);
                mma16816(d, ah0, ah1, ah2, ah3, Bl[kt][0], Bl[kt][1]);
            }
            float* gg = (role == 0) ? gg0 : (role == 1) ? ggX : gg1;
            float* gp = gg + r * 10 + c0;
            *(float2*)gp            = make_float2(d[0], d[1]);
            *(float2*)(gp + 8 * 10) = make_float2(d[2], d[3]);
        }
        __syncthreads();

        const bool active = (tid < 256) && ((l_ == 0) ? (s < Tc) : (s >= 1));
        if (active) {
            float gate[4];
#pragma unroll
            for (int g = 0; g < 4; g++) {
                int c = g * 2 + u_;
                gate[g] = (l_ == 0) ? (gg0[b_ * 10 + c] + pf[g])
                                    : (ggX[b_ * 10 + c] + gg1[b_ * 10 + c] + b1sh[c]);
            }
            float ii = sigf(gate[0]);
            float jj = tanhf_(gate[1]);
            float ff = sigf(gate[2] + 1.0f);       // FORGET_BIAS
            float oo = sigf(gate[3]);
            creg = creg * ff + ii * jj;
            float h = tanhf_(creg) * oo;
            int off = b_ * Hc + U_;
            if (l_ == 0) {
                g_h0p[(s + 1) & 1][off] = packsplit(h);
            } else if (s < Tc) {
                g_h1p[(s + 1) & 1][off] = packsplit(h);
            } else {
                out[off] = h;                       // h1[T-1]
            }
        }
        if (s < Tc) gbar(bid, tid, (unsigned)(s + 2));
    }
}

// ---------------- k_reset ----------------
__global__ void k_reset() {
    int i = blockIdx.x * blockDim.x + threadIdx.x;
    if (i < NB * 8) g_flags[i] = 0u;
    if (i == 0) g_gen = 0u;
}

// ---------------- host launcher ----------------
extern "C" void kernel_launch(void* const* d_in, const int* in_sizes, int n_in,
                              void* d_out, int out_size) {
    const int*   x   = (const int*)d_in[0];
    const float* emb = (const float*)d_in[1];
    const float* W0  = (const float*)d_in[2];
    const float* b0  = (const float*)d_in[3];
    const float* W1  = (const float*)d_in[4];
    const float* b1  = (const float*)d_in[5];
    float*       out = (float*)d_out;
    (void)in_sizes; (void)n_in; (void)out_size;

    const int smem_pre = Ec * 66 * 4;                         // 79200 B
    const int smem_rnn = 2 * Bc * SROW * 4 + 3 * Bc * 10 * 4 + 32;  // 140832 B

    static bool attr_done = false;
    if (!attr_done) {
        cudaFuncSetAttribute(k_pre, cudaFuncAttributeMaxDynamicSharedMemorySize, smem_pre);
        cudaFuncSetAttribute(k_rnn, cudaFuncAttributeMaxDynamicSharedMemorySize, smem_rnn);
        attr_done = true;
    }

    k_detect<<<1, 512>>>(x);
    k_pre<<<dim3(4, 256), 256, smem_pre>>>(x, emb, W0, b0);
    k_reset<<<4, 256>>>();
    k_rnn<<<NB, NT, smem_rnn>>>(W0, W1, b1, out);
}

// round 16
// speedup vs baseline: 1.6741x; 1.3900x over previous
#include <cuda_runtime.h>
#include <cuda_bf16.h>
#include <cstdint>

#define Hc   256
#define Bc   64
#define Tc   256
#define Ec   300
#define NB   128
#define NT   384
#define SROW 260
typedef unsigned long long ull;
typedef unsigned int u32;

// ---------------- device scratch ----------------
__device__ float g_pre0[(size_t)Tc * 1024 * Bc];   // [t][gatecol][b]
__device__ u32 g_h0p[2][Bc * Hc];                  // packed split h0 [slot][b][unit]
__device__ u32 g_h1p[2][Bc * Hc];                  // packed split h1
__device__ unsigned g_flags[NB * 8];
__device__ unsigned g_gen4[4 * 8];                 // per-group generation words
__device__ int g_is64;

// ---------------- helpers ----------------
__device__ __forceinline__ void fma2(ull& d, ull a, ull b) {
    asm("fma.rn.f32x2 %0, %1, %2, %0;" : "+l"(d) : "l"(a), "l"(b));
}
__device__ __forceinline__ ull dup2(float x) {
    ull r; asm("mov.b64 %0, {%1, %1};" : "=l"(r) : "f"(x)); return r;
}
__device__ __forceinline__ float2 unpk(ull v) {
    float2 r; asm("mov.b64 {%0, %1}, %2;" : "=f"(r.x), "=f"(r.y) : "l"(v)); return r;
}
__device__ __forceinline__ float sigf(float x)  { return 1.0f / (1.0f + __expf(-x)); }
__device__ __forceinline__ float tanhf_(float x){ return 2.0f / (1.0f + __expf(-2.0f * x)) - 1.0f; }
__device__ __forceinline__ void st_rel(unsigned* p, unsigned v) {
    asm volatile("st.release.gpu.global.u32 [%0], %1;" :: "l"(p), "r"(v) : "memory");
}
__device__ __forceinline__ unsigned ld_acq(const unsigned* p) {
    unsigned v; asm volatile("ld.acquire.gpu.global.u32 %0, [%1];" : "=r"(v) : "l"(p) : "memory");
    return v;
}
__device__ __forceinline__ u32 prmt(u32 a, u32 b, u32 s) {
    u32 r; asm("prmt.b32 %0, %1, %2, %3;" : "=r"(r) : "r"(a), "r"(b), "r"(s)); return r;
}
__device__ __forceinline__ void mma16816(float* d, u32 a0, u32 a1, u32 a2, u32 a3,
                                         u32 b0, u32 b1) {
    asm("mma.sync.aligned.m16n8k16.row.col.f32.bf16.bf16.f32 "
        "{%0,%1,%2,%3}, {%4,%5,%6,%7}, {%8,%9}, {%0,%1,%2,%3};"
        : "+f"(d[0]), "+f"(d[1]), "+f"(d[2]), "+f"(d[3])
        : "r"(a0), "r"(a1), "r"(a2), "r"(a3), "r"(b0), "r"(b1));
}
__device__ __forceinline__ void split(float v, u32& hb, u32& lb) {
    __nv_bfloat16 h = __float2bfloat16(v);
    float r = v - __bfloat162float(h);
    hb = (u32)__bfloat16_as_ushort(h);
    lb = (u32)__bfloat16_as_ushort(__float2bfloat16(r));
}
__device__ __forceinline__ u32 packsplit(float v) {
    u32 hb, lb; split(v, hb, lb); return hb | (lb << 16);
}

// Per-group barrier (32 CTAs): per-CTA release flag; group leader (ub==0)
// aggregates its 32 flags (1/lane) and publishes the group gen word.
__device__ __forceinline__ void gbar(int gr, int ub, int bid, int tid, unsigned epoch) {
    __syncthreads();
    if (tid == 0) st_rel(&g_flags[bid * 8], epoch);
    if (ub == 0 && tid < 32) {
        bool ok;
        do {
            unsigned v = ld_acq(&g_flags[(gr * 32 + tid) * 8]);
            ok = (v >= epoch);
        } while (!__all_sync(0xffffffffu, ok));
        if (tid == 0) st_rel(&g_gen4[gr * 8], epoch);
    } else if (tid == 0) {
        while (ld_acq(&g_gen4[gr * 8]) < epoch) {}
    }
    __syncthreads();
}

// ---------------- int32/int64 token detector ----------------
__global__ void k_detect(const int* __restrict__ x) {
    int v = 0;
    for (int i = threadIdx.x * 2 + 1; i < Bc * Tc; i += 1024) v |= x[i];
    int any = __syncthreads_or(v);
    if (threadIdx.x == 0) g_is64 = (any == 0) ? 1 : 0;
}

// ---------------- k_pre: x-projection (proven) ----------------
__global__ void __launch_bounds__(256) k_pre(const int* __restrict__ x,
                                             const float* __restrict__ emb,
                                             const float* __restrict__ W0,
                                             const float* __restrict__ b0) {
    extern __shared__ float semb[];
    const int t = blockIdx.y, ct = blockIdx.x;
    const int tid = threadIdx.x, lane = tid & 31, w = tid >> 5;
    const int is64 = g_is64;

    for (int bb = w; bb < Bc; bb += 8) {
        int idx = bb * Tc + t;
        int tok = is64 ? x[2 * idx] : x[idx];
        const float* er = emb + (size_t)tok * Ec;
        for (int e = lane; e < Ec; e += 32) semb[e * 66 + bb] = er[e];
    }
    __syncthreads();

    const int cg = tid & 63, bg = tid >> 6;
    const int c0 = ct * 256 + cg * 4;

    ull a0[8], a1[8], a2[8], a3[8];
#pragma unroll
    for (int j = 0; j < 8; j++) { a0[j] = 0ull; a1[j] = 0ull; a2[j] = 0ull; a3[j] = 0ull; }

#pragma unroll 4
    for (int e = 0; e < Ec; e++) {
        float4 wv = __ldg((const float4*)(W0 + (size_t)e * 1024 + c0));
        ull w0 = dup2(wv.x), w1 = dup2(wv.y), w2 = dup2(wv.z), w3 = dup2(wv.w);
        const ull* sp = (const ull*)(semb + e * 66 + bg * 16);
        ull p0 = sp[0], p1 = sp[1], p2 = sp[2], p3 = sp[3];
        ull p4 = sp[4], p5 = sp[5], p6 = sp[6], p7 = sp[7];
        fma2(a0[0], p0, w0); fma2(a0[1], p1, w0); fma2(a0[2], p2, w0); fma2(a0[3], p3, w0);
        fma2(a0[4], p4, w0); fma2(a0[5], p5, w0); fma2(a0[6], p6, w0); fma2(a0[7], p7, w0);
        fma2(a1[0], p0, w1); fma2(a1[1], p1, w1); fma2(a1[2], p2, w1); fma2(a1[3], p3, w1);
        fma2(a1[4], p4, w1); fma2(a1[5], p5, w1); fma2(a1[6], p6, w1); fma2(a1[7], p7, w1);
        fma2(a2[0], p0, w2); fma2(a2[1], p1, w2); fma2(a2[2], p2, w2); fma2(a2[3], p3, w2);
        fma2(a2[4], p4, w2); fma2(a2[5], p5, w2); fma2(a2[6], p6, w2); fma2(a2[7], p7, w2);
        fma2(a3[0], p0, w3); fma2(a3[1], p1, w3); fma2(a3[2], p2, w3); fma2(a3[3], p3, w3);
        fma2(a3[4], p4, w3); fma2(a3[5], p5, w3); fma2(a3[6], p6, w3); fma2(a3[7], p7, w3);
    }

    float4 bb4 = __ldg((const float4*)(b0 + c0));
    float bs[4] = {bb4.x, bb4.y, bb4.z, bb4.w};
    ull* accs[4] = {a0, a1, a2, a3};
#pragma unroll
    for (int j = 0; j < 4; j++) {
        float* op = g_pre0 + ((size_t)t * 1024 + c0 + j) * Bc + bg * 16;
#pragma unroll
        for (int p = 0; p < 8; p++) {
            float2 v = unpk(accs[j][p]);
            v.x += bs[j]; v.y += bs[j];
            *(float2*)(op + 2 * p) = v;
        }
    }
}

// ---------------- k_rnn: batch-grouped tensor-core recurrence ----------------
// 4 groups x 16 batches; 32 CTAs/group; CTA owns 8 units x 16 batches (both layers).
// Sync = per-group 32-CTA barrier. Per CTA/step: stage group h (32KB) to smem,
// 12 warps x 48 HMMA (role 0=W0h, 1=W1x, 2=W1h; n-tile = wid&3, M=16), 256
// activation threads. Fragment math identical to verified R12.
__global__ void __launch_bounds__(NT) k_rnn(const float* __restrict__ W0,
                                            const float* __restrict__ W1,
                                            const float* __restrict__ b1,
                                            float* __restrict__ out) {
    __shared__ u32 sh0[16 * SROW], sh1[16 * SROW];
    __shared__ float gg0[16 * 34], ggX[16 * 34], gg1[16 * 34], b1sh[32];

    const int tid = threadIdx.x, lane = tid & 31, wid = tid >> 5, bid = blockIdx.x;
    const int role = wid >> 2;
    const int ub = bid & 31, gr = bid >> 5;        // unit-slice, batch-group
    const int ubase = ub * 8, bbase = gr * 16;

    // persistent weight B-fragments (verified layout; col c = (wid&3)*8 + n)
    u32 Bh[16][2], Bl[16][2];
    {
        const int n = lane >> 2, k0 = (lane & 3) * 2;
        const int c = (wid & 3) * 8 + n;
        const int G = (c >> 3) * 256 + ubase + (c & 7);
        const float* Wp = (role == 0) ? W0 + (size_t)Ec * 1024
                        : (role == 1) ? W1
                                      : W1 + (size_t)Hc * 1024;
#pragma unroll
        for (int kt = 0; kt < 16; kt++)
#pragma unroll
            for (int j = 0; j < 2; j++) {
                int k = kt * 16 + j * 8 + k0;
                u32 h0b, l0b, h1b, l1b;
                split(__ldg(Wp + (size_t)k * 1024 + G), h0b, l0b);
                split(__ldg(Wp + (size_t)(k + 1) * 1024 + G), h1b, l1b);
                Bh[kt][j] = h0b | (h1b << 16);
                Bl[kt][j] = l0b | (l1b << 16);
            }
    }
    if (tid < 32) {
        int c = tid, G = (c >> 3) * 256 + ubase + (c & 7);
        b1sh[c] = __ldg(b1 + G);
    }
    // zero owned h entries in both slots
    if (tid < 256) {
        int l = tid >> 7, u = (tid >> 4) & 7, b = tid & 15;
        int off = (bbase + b) * Hc + ubase + u;
        if (l == 0) { g_h0p[0][off] = 0u; g_h0p[1][off] = 0u; }
        else        { g_h1p[0][off] = 0u; g_h1p[1][off] = 0u; }
    }
    float creg = 0.f;
    gbar(gr, ub, bid, tid, 1u);

    const int l_ = tid >> 7, u_ = (tid >> 4) & 7, b_ = tid & 15;
    const int U_ = ubase + u_;

    for (int s = 0; s <= Tc; s++) {
        float pf[4] = {0.f, 0.f, 0.f, 0.f};
        if (tid < 128 && s < Tc) {
#pragma unroll
            for (int g = 0; g < 4; g++)
                pf[g] = __ldg(g_pre0 + ((size_t)s * 1024 + g * 256 + U_) * Bc + bbase + b_);
        }

        // ---- stage this group's h0/h1 (16 batches x 256 u32 each) into smem ----
        {
            const uint4* s0 = (const uint4*)(g_h0p[s & 1] + bbase * Hc);
            const uint4* s1 = (const uint4*)(g_h1p[s & 1] + bbase * Hc);
#pragma unroll
            for (int it = 0; it < 3; it++) {
                int q = it * NT + tid;           // uint4 index, 1024 per buffer
                if (q < 1024) {
                    int b = q >> 6, u = (q & 63) * 4;
                    *(uint4*)(sh0 + b * SROW + u) = __ldcg(s0 + q);
                    *(uint4*)(sh1 + b * SROW + u) = __ldcg(s1 + q);
                }
            }
        }
        __syncthreads();

        const bool go = (role == 0) ? (s < Tc) : (s >= 1);
        if (go) {
            const u32* hp = (role < 2) ? sh0 : sh1;
            const int r = lane >> 2, c0 = (lane & 3) * 2;
            const u32* base0 = hp + r * SROW;
            const u32* base1 = hp + (r + 8) * SROW;
            float d[4] = {0.f, 0.f, 0.f, 0.f};
#pragma unroll
            for (int kt = 0; kt < 16; kt++) {
                int c = kt * 16 + c0;
                ull q0 = *(const ull*)(base0 + c);
                ull q1 = *(const ull*)(base1 + c);
                ull q2 = *(const ull*)(base0 + c + 8);
                ull q3 = *(const ull*)(base1 + c + 8);
                u32 ah0 = prmt((u32)q0, (u32)(q0 >> 32), 0x5410);
                u32 al0 = prmt((u32)q0, (u32)(q0 >> 32), 0x7632);
                u32 ah1 = prmt((u32)q1, (u32)(q1 >> 32), 0x5410);
                u32 al1 = prmt((u32)q1, (u32)(q1 >> 32), 0x7632);
                u32 ah2 = prmt((u32)q2, (u32)(q2 >> 32), 0x5410);
                u32 al2 = prmt((u32)q2, (u32)(q2 >> 32), 0x7632);
                u32 ah3 = prmt((u32)q3, (u32)(q3 >> 32), 0x5410);
                u32 al3 = prmt((u32)q3, (u32)(q3 >> 32), 0x7632);
                mma16816(d, ah0, ah1, ah2, ah3, Bh[kt][0], Bh[kt][1]);
                mma16816(d, al0, al1, al2, al3, Bh[kt][0], Bh[kt][1]);
                mma16816(d, ah0, ah1, ah2, ah3, Bl[kt][0], Bl[kt][1]);
            }
            float* gg = (role == 0) ? gg0 : (role == 1) ? ggX : gg1;
            float* gp = gg + r * 34 + (wid & 3) * 8 + c0;
            *(float2*)gp            = make_float2(d[0], d[1]);
            *(float2*)(gp + 8 * 34) = make_float2(d[2], d[3]);
        }
        __syncthreads();

        const bool active = (tid < 256) && ((l_ == 0) ? (s < Tc) : (s >= 1));
        if (active) {
            float gate[4];
#pragma unroll
            for (int g = 0; g < 4; g++) {
                int c = g * 8 + u_;
                gate[g] = (l_ == 0) ? (gg0[b_ * 34 + c] + pf[g])
                                    : (ggX[b_ * 34 + c] + gg1[b_ * 34 + c] + b1sh[c]);
            }
            float ii = sigf(gate[0]);
            float jj = tanhf_(gate[1]);
            float ff = sigf(gate[2] + 1.0f);       // FORGET_BIAS
            float oo = sigf(gate[3]);
            creg = creg * ff + ii * jj;
            float h = tanhf_(creg) * oo;
            int off = (bbase + b_) * Hc + U_;
            if (l_ == 0) {
                g_h0p[(s + 1) & 1][off] = packsplit(h);
            } else if (s < Tc) {
                g_h1p[(s + 1) & 1][off] = packsplit(h);
            } else {
                out[off] = h;                       // h1[T-1]
            }
        }
        if (s < Tc) gbar(gr, ub, bid, tid, (unsigned)(s + 2));
    }
}

// ---------------- k_reset ----------------
__global__ void k_reset() {
    int i = blockIdx.x * blockDim.x + threadIdx.x;
    if (i < NB * 8) g_flags[i] = 0u;
    if (i < 4 * 8) g_gen4[i] = 0u;
}

// ---------------- host launcher ----------------
extern "C" void kernel_launch(void* const* d_in, const int* in_sizes, int n_in,
                              void* d_out, int out_size) {
    const int*   x   = (const int*)d_in[0];
    const float* emb = (const float*)d_in[1];
    const float* W0  = (const float*)d_in[2];
    const float* b0  = (const float*)d_in[3];
    const float* W1  = (const float*)d_in[4];
    const float* b1  = (const float*)d_in[5];
    float*       out = (float*)d_out;
    (void)in_sizes; (void)n_in; (void)out_size;

    const int smem_pre = Ec * 66 * 4;   // 79200 B

    static bool attr_done = false;
    if (!attr_done) {
        cudaFuncSetAttribute(k_pre, cudaFuncAttributeMaxDynamicSharedMemorySize, smem_pre);
        attr_done = true;
    }

    k_detect<<<1, 512>>>(x);
    k_pre<<<dim3(4, 256), 256, smem_pre>>>(x, emb, W0, b0);
    k_reset<<<4, 256>>>();
    k_rnn<<<NB, NT>>>(W0, W1, b1, out);
}